// round 4
// baseline (speedup 1.0000x reference)
#include <cuda_runtime.h>
#include <cstdint>

// Fully fused Precoding-GNN, R4: one sample per 2-CTA cluster, hidden state
// resident in SMEM across all 5 layers.
// Edge GEMM: E=4 edges x H=16 outputs per thread, f32x2 FMA, LDS.128 h loads.
// msg_m fused into edge epilogue (shfl tree); msg_k via scalar column pass.
// Bias GEMMs in f32x2 with transposed staged weights. float2 DSMEM combine.
// BS=1024, M=64, K=32, D=32. Each CTA owns 32 antennas -> 1024 edges.
// h layout: h[d][e], e = m_loc*32 + k (pitch 1024 floats).

#define NT 512
#define NW 16

typedef unsigned long long ull;

struct SM {
  float h[32 * 1024];      // 131072 B hidden state [d][e]
  float xs[2 * 1024];      //   8192 B layer-1 input [c][e]
  float wsT[1024];         //   4096 B Ws^T: wsT[d*32+h] (stride 2 for L5)
  float wmT[1024];         //   4096 B Wm^T: wmT[d*32+h]
  float wkT[1024];         //   4096 B Wk^T
  float mm[32 * 34];       //   4352 B msg_m[m][d]      (pitch 34)
  float mkpL[2][32 * 34];  //   8704 B msg_k partial [k][d], parity buffered
  float mkc[32 * 34];      //   4352 B msg_k combined [k][d]
  float bm[32 * 34];       //   4352 B Wm@msg_m  [m][h]
  float bk[32 * 34];       //   4352 B Wk@msg_k  [k][h]
  float red[NW];
  float powslot;
};

struct Params {
  const float* x;
  const float* w[15];
  float* out;
};

extern __shared__ __align__(16) char smem_raw[];

__device__ __forceinline__ uint32_t s2u(const void* p) {
  uint32_t a;
  asm("{ .reg .u64 t; cvta.to.shared.u64 t, %1; cvt.u32.u64 %0, t; }"
      : "=r"(a) : "l"(p));
  return a;
}
__device__ __forceinline__ float peer_ldf(const float* p, uint32_t peer) {
  uint32_t ra;
  asm("mapa.shared::cluster.u32 %0, %1, %2;" : "=r"(ra) : "r"(s2u(p)), "r"(peer));
  float v;
  asm volatile("ld.shared::cluster.f32 %0, [%1];" : "=f"(v) : "r"(ra));
  return v;
}
__device__ __forceinline__ float2 peer_ldf2(const float* p, uint32_t peer) {
  uint32_t ra;
  asm("mapa.shared::cluster.u32 %0, %1, %2;" : "=r"(ra) : "r"(s2u(p)), "r"(peer));
  float2 v;
  asm volatile("ld.shared::cluster.v2.f32 {%0,%1}, [%2];"
               : "=f"(v.x), "=f"(v.y) : "r"(ra));
  return v;
}
__device__ __forceinline__ void csync() {
  asm volatile("barrier.cluster.arrive.aligned;" ::: "memory");
  asm volatile("barrier.cluster.wait.aligned;" ::: "memory");
}
__device__ __forceinline__ ull pk2(float x, float y) {
  ull r; asm("mov.b64 %0,{%1,%2};" : "=l"(r) : "f"(x), "f"(y)); return r;
}
__device__ __forceinline__ void upk2(ull v, float& x, float& y) {
  asm("mov.b64 {%0,%1},%2;" : "=f"(x), "=f"(y) : "l"(v));
}
__device__ __forceinline__ void fma2(ull& d, ull a, ull b) {
  asm("fma.rn.f32x2 %0,%1,%2,%0;" : "+l"(d) : "l"(a), "l"(b));
}
__device__ __forceinline__ ull add2(ull a, ull b) {
  ull r; asm("add.rn.f32x2 %0,%1,%2;" : "=l"(r) : "l"(a), "l"(b)); return r;
}

// msg_k partial: mkp[k][d] = sum_{m_loc} src[d][m*32+k]
template <int DIN>
__device__ __forceinline__ void mkp_pass(const float* src, float* mkp,
                                         int lane, int wid) {
  for (int d = wid; d < DIN; d += NW) {
    float t = 0.f;
#pragma unroll
    for (int m2 = 0; m2 < 32; m2++) t += src[d * 1024 + m2 * 32 + lane];
    mkp[lane * 34 + d] = t;
  }
}

// combine: mkc = mkp(local) + mkp(peer), DIN even, float2 granularity
template <int DIN>
__device__ __forceinline__ void combine_mk(SM* s, const float* mkp, int tid,
                                           uint32_t peer) {
  constexpr int PAIRS = 32 * DIN / 2;
  for (int i = tid; i < PAIRS; i += NT) {
    int k = i / (DIN / 2), dp = i % (DIN / 2);
    int off = k * 34 + 2 * dp;
    float2 a = *(const float2*)(mkp + off);
    float2 b = peer_ldf2(mkp + off, peer);
    *(float2*)(s->mkc + off) = make_float2(a.x + b.x, a.y + b.y);
  }
}

// bias GEMMs (DOUT=32): bm[mk][h] = WmT^T@mm, bk[mk][h] = WkT^T@mkc
template <int DIN>
__device__ __forceinline__ void bias_gemm(SM* s, int tid) {
  const int jj = tid & 15, mk = tid >> 4;  // 32 mk x 16 h-pairs
  ull tb = 0, tk = 0;
#pragma unroll
  for (int d = 0; d < DIN; d++) {
    ull wmv = *(const ull*)(s->wmT + d * 32 + 2 * jj);
    ull wkv = *(const ull*)(s->wkT + d * 32 + 2 * jj);
    float am = s->mm[mk * 34 + d];
    float ak = s->mkc[mk * 34 + d];
    fma2(tb, pk2(am, am), wmv);
    fma2(tk, pk2(ak, ak), wkv);
  }
  float a, b;
  upk2(tb, a, b); *(float2*)(s->bm + mk * 34 + 2 * jj) = make_float2(a, b);
  upk2(tk, a, b); *(float2*)(s->bk + mk * 34 + 2 * jj) = make_float2(a, b);
}

// One GNN layer, DOUT=32. src = xs (L1) or h (L2-4). Writes relu(z) to h and
// mm for the NEXT layer. par = parity of mkpL buffer for THIS layer.
template <int DIN, bool FIRST>
__device__ __forceinline__ void layer32(SM* s, const float* src,
                                        const float* gWs, const float* gWm,
                                        const float* gWk, int par, int tid,
                                        int lane, int wid, uint32_t peer) {
  float* mkp = s->mkpL[par];
  // stage transposed weights
  for (int i = tid; i < DIN * 32; i += NT) {
    int d = i >> 5, hh = i & 31;
    s->wsT[i] = gWs[hh * DIN + d];
    s->wmT[i] = gWm[hh * DIN + d];
    s->wkT[i] = gWk[hh * DIN + d];
  }
  mkp_pass<DIN>(src, mkp, lane, wid);
  if (FIRST) {
    // mm from xs: mm[m][c] = sum_k xs[c][m*32+k]
    for (int r = wid; r < DIN * 8; r += NW) {
      int c = r >> 3, g = r & 7;
      float4 v = *(const float4*)(src + c * 1024 + g * 128 + lane * 4);
      float t = v.x + v.y + v.z + v.w;
      t += __shfl_xor_sync(0xffffffffu, t, 1);
      t += __shfl_xor_sync(0xffffffffu, t, 2);
      t += __shfl_xor_sync(0xffffffffu, t, 4);
      if ((lane & 7) == 0) s->mm[(g * 4 + (lane >> 3)) * 34 + c] = t;
    }
  }
  csync();  // mkp visible cluster-wide; also CTA-local barrier for staging/mm
  combine_mk<DIN>(s, mkp, tid, peer);
  __syncthreads();
  bias_gemm<DIN>(s, tid);
  __syncthreads();

  // ---- edge GEMM: warp covers 128 edges x 16 h; thread: 4 edges x 16 h ----
  const int ht = wid >> 3, eg = wid & 7;
  const int hb = ht * 16;
  const int e0 = eg * 128 + lane * 4;
  const int m = e0 >> 5;
  const int k0 = 4 * (lane & 7);

  ull acc[4][8];
  {
    float2 bmv[8];
#pragma unroll
    for (int j = 0; j < 8; j++)
      bmv[j] = *(const float2*)(s->bm + m * 34 + hb + 2 * j);
#pragma unroll
    for (int e = 0; e < 4; e++) {
#pragma unroll
      for (int j = 0; j < 8; j++) {
        float2 bkv = *(const float2*)(s->bk + (k0 + e) * 34 + hb + 2 * j);
        acc[e][j] = pk2(bmv[j].x + bkv.x, bmv[j].y + bkv.y);
      }
    }
  }
#pragma unroll 4
  for (int d = 0; d < DIN; d++) {
    float4 hv = *(const float4*)(src + d * 1024 + e0);
    ull H0 = pk2(hv.x, hv.x), H1 = pk2(hv.y, hv.y);
    ull H2 = pk2(hv.z, hv.z), H3 = pk2(hv.w, hv.w);
    const ulonglong2* wr = (const ulonglong2*)(s->wsT + d * 32 + hb);
#pragma unroll
    for (int q = 0; q < 4; q++) {
      ulonglong2 w = wr[q];
      fma2(acc[0][2 * q], H0, w.x); fma2(acc[0][2 * q + 1], H0, w.y);
      fma2(acc[1][2 * q], H1, w.x); fma2(acc[1][2 * q + 1], H1, w.y);
      fma2(acc[2][2 * q], H2, w.x); fma2(acc[2][2 * q + 1], H2, w.y);
      fma2(acc[3][2 * q], H3, w.x); fma2(acc[3][2 * q + 1], H3, w.y);
    }
  }
  __syncthreads();  // all reads of src complete before in-place writes

  // ---- epilogue: relu + store h + fused msg_m for next layer ----
#pragma unroll
  for (int j = 0; j < 8; j++) {
    float v[8];
#pragma unroll
    for (int e = 0; e < 4; e++) {
      float a, b;
      upk2(acc[e][j], a, b);
      v[2 * e] = fmaxf(a, 0.f);
      v[2 * e + 1] = fmaxf(b, 0.f);
    }
    *(float4*)(s->h + (hb + 2 * j) * 1024 + e0) =
        make_float4(v[0], v[2], v[4], v[6]);
    *(float4*)(s->h + (hb + 2 * j + 1) * 1024 + e0) =
        make_float4(v[1], v[3], v[5], v[7]);
    ull t = add2(add2(pk2(v[0], v[1]), pk2(v[2], v[3])),
                 add2(pk2(v[4], v[5]), pk2(v[6], v[7])));
    t = add2(t, __shfl_xor_sync(0xffffffffu, t, 1));
    t = add2(t, __shfl_xor_sync(0xffffffffu, t, 2));
    t = add2(t, __shfl_xor_sync(0xffffffffu, t, 4));
    if ((lane & 7) == 0) {
      float lo, hi;
      upk2(t, lo, hi);
      *(float2*)(s->mm + m * 34 + hb + 2 * j) = make_float2(lo, hi);
    }
  }
  __syncthreads();  // h, mm ready for next layer
}

__global__ void __launch_bounds__(NT, 1) __cluster_dims__(2, 1, 1)
gnn_kernel(Params p) {
  SM* s = (SM*)smem_raw;
  const int tid = threadIdx.x, lane = tid & 31, wid = tid >> 5;
  uint32_t rank;
  asm("mov.u32 %0, %%cluster_ctarank;" : "=r"(rank));
  const uint32_t peer = rank ^ 1u;
  const int sample = blockIdx.x >> 1;

  // stage x -> xs[c][e]
  {
    const float* xg = p.x + (size_t)sample * 4096 + (size_t)rank * 2048;
    float4 v = *(const float4*)(xg + 4 * tid);
    int e0 = 2 * tid;
    s->xs[e0] = v.x; s->xs[e0 + 1] = v.z;
    s->xs[1024 + e0] = v.y; s->xs[1024 + e0 + 1] = v.w;
  }
  __syncthreads();

  // parities: L1:0 L2:1 L3:0 L4:1 L5:0 (overwrite distance 2 => safe)
  layer32<2, true>(s, s->xs, p.w[0], p.w[1], p.w[2], 0, tid, lane, wid, peer);
  for (int l = 1; l < 4; ++l)
    layer32<32, false>(s, s->h, p.w[3 * l], p.w[3 * l + 1], p.w[3 * l + 2],
                       l & 1, tid, lane, wid, peer);

  // ---- layer 5 (DIN=32, DOUT=2, no relu) + power norm + store ----
  {
    const float* gWs = p.w[12];
    const float* gWm = p.w[13];
    const float* gWk = p.w[14];
    float* mkp = s->mkpL[0];
    for (int i = tid; i < 64; i += NT) {  // transposed stride-2 staging
      int d = i >> 1, hh = i & 1;
      s->wsT[d * 2 + hh] = gWs[hh * 32 + d];
      s->wmT[d * 2 + hh] = gWm[hh * 32 + d];
      s->wkT[d * 2 + hh] = gWk[hh * 32 + d];
    }
    mkp_pass<32>(s->h, mkp, lane, wid);
    csync();
    combine_mk<32>(s, mkp, tid, peer);
    __syncthreads();
    if (tid < 32) {  // bias: 32 mk x 1 h-pair each, bm and bk
      ull tb = 0, tk = 0;
#pragma unroll
      for (int d = 0; d < 32; d++) {
        ull wmv = *(const ull*)(s->wmT + d * 2);
        ull wkv = *(const ull*)(s->wkT + d * 2);
        float am = s->mm[tid * 34 + d];
        float ak = s->mkc[tid * 34 + d];
        fma2(tb, pk2(am, am), wmv);
        fma2(tk, pk2(ak, ak), wkv);
      }
      float a, b;
      upk2(tb, a, b); *(float2*)(s->bm + tid * 34) = make_float2(a, b);
      upk2(tk, a, b); *(float2*)(s->bk + tid * 34) = make_float2(a, b);
    }
    __syncthreads();

    const int e0 = 2 * tid, m = e0 >> 5, k0 = e0 & 31;
    float2 bmv = *(const float2*)(s->bm + m * 34);
    float2 b0v = *(const float2*)(s->bk + k0 * 34);
    float2 b1v = *(const float2*)(s->bk + (k0 + 1) * 34);
    ull a0 = pk2(bmv.x + b0v.x, bmv.y + b0v.y);
    ull a1 = pk2(bmv.x + b1v.x, bmv.y + b1v.y);
#pragma unroll 8
    for (int d = 0; d < 32; d++) {
      float2 hv = *(const float2*)(s->h + d * 1024 + e0);
      ull w = *(const ull*)(s->wsT + d * 2);
      fma2(a0, pk2(hv.x, hv.x), w);
      fma2(a1, pk2(hv.y, hv.y), w);
    }
    float x0, x1, y0, y1;
    upk2(a0, x0, x1);
    upk2(a1, y0, y1);

    // power = sum over whole sample of z^2
    float pl = x0 * x0 + x1 * x1 + y0 * y0 + y1 * y1;
    pl += __shfl_xor_sync(0xffffffffu, pl, 1);
    pl += __shfl_xor_sync(0xffffffffu, pl, 2);
    pl += __shfl_xor_sync(0xffffffffu, pl, 4);
    pl += __shfl_xor_sync(0xffffffffu, pl, 8);
    pl += __shfl_xor_sync(0xffffffffu, pl, 16);
    if (lane == 0) s->red[wid] = pl;
    __syncthreads();
    if (tid == 0) {
      float t = 0.f;
#pragma unroll
      for (int w2 = 0; w2 < NW; w2++) t += s->red[w2];
      s->powslot = t;
    }
    csync();  // both CTAs' powslot ready
    float al = rsqrtf(s->powslot + peer_ldf(&s->powslot, peer));  // PT = 1

    float4 o = make_float4(al * x0, al * x1, al * y0, al * y1);
    *(float4*)(p.out + (size_t)sample * 4096 + (size_t)rank * 2048 + 4 * tid) = o;
    csync();  // keep our smem alive until peer finished its powslot read
  }
}

extern "C" void kernel_launch(void* const* d_in, const int* in_sizes, int n_in,
                              void* d_out, int out_size) {
  Params p;
  p.x = (const float*)d_in[0];
  for (int i = 0; i < 15; i++) p.w[i] = (const float*)d_in[1 + i];
  p.out = (float*)d_out;
  cudaFuncSetAttribute(gnn_kernel, cudaFuncAttributeMaxDynamicSharedMemorySize,
                       (int)sizeof(SM));
  gnn_kernel<<<2048, NT, sizeof(SM)>>>(p);
}

// round 5
// speedup vs baseline: 1.5642x; 1.5642x over previous
#include <cuda_runtime.h>
#include <cstdint>

// Fully fused Precoding-GNN, R5: R3 structure at NT=1024 (32 warps, 8/SMSP).
// One sample per 2-CTA cluster, hidden state resident in SMEM for all 5
// layers. Edge GEMM: 2 edges x 16 outputs per thread (h-split 2), f32x2 FMA.
// BS=1024, M=64, K=32, D=32. Each CTA owns 32 antennas -> 1024 edges.
// h layout: h[d][e], e = m_loc*32 + k (pitch 1024 floats).

#define NT 1024
#define NW 32

typedef unsigned long long ull;

struct SM {
  float h[32 * 1024];      // 131072 B hidden state [d][e]
  float xs[2 * 1024];      //   8192 B layer-1 input [c][e]
  float wsT[1024];         //   4096 B Ws^T: wsT[d*32+h] (stride 2 for L5)
  float wmT[1024];         //   4096 B Wm^T: wmT[d*32+h]
  float wkT[1024];         //   4096 B Wk^T
  float mm[32 * 34];       //   4352 B msg_m[m][d]      (pitch 34)
  float mkpL[2][32 * 34];  //   8704 B msg_k partial [k][d], parity buffered
  float mkc[32 * 34];      //   4352 B msg_k combined [k][d]
  float bm[32 * 34];       //   4352 B Wm@msg_m  [m][h]
  float bk[32 * 34];       //   4352 B Wk@msg_k  [k][h]
  float red[NW];
  float powslot;
};

struct Params {
  const float* x;
  const float* w[15];
  float* out;
};

extern __shared__ __align__(16) char smem_raw[];

__device__ __forceinline__ uint32_t s2u(const void* p) {
  uint32_t a;
  asm("{ .reg .u64 t; cvta.to.shared.u64 t, %1; cvt.u32.u64 %0, t; }"
      : "=r"(a) : "l"(p));
  return a;
}
__device__ __forceinline__ float peer_ldf(const float* p, uint32_t peer) {
  uint32_t ra;
  asm("mapa.shared::cluster.u32 %0, %1, %2;" : "=r"(ra) : "r"(s2u(p)), "r"(peer));
  float v;
  asm volatile("ld.shared::cluster.f32 %0, [%1];" : "=f"(v) : "r"(ra));
  return v;
}
__device__ __forceinline__ float2 peer_ldf2(const float* p, uint32_t peer) {
  uint32_t ra;
  asm("mapa.shared::cluster.u32 %0, %1, %2;" : "=r"(ra) : "r"(s2u(p)), "r"(peer));
  float2 v;
  asm volatile("ld.shared::cluster.v2.f32 {%0,%1}, [%2];"
               : "=f"(v.x), "=f"(v.y) : "r"(ra));
  return v;
}
__device__ __forceinline__ void csync() {
  asm volatile("barrier.cluster.arrive.aligned;" ::: "memory");
  asm volatile("barrier.cluster.wait.aligned;" ::: "memory");
}
__device__ __forceinline__ ull pk2(float x, float y) {
  ull r; asm("mov.b64 %0,{%1,%2};" : "=l"(r) : "f"(x), "f"(y)); return r;
}
__device__ __forceinline__ void upk2(ull v, float& x, float& y) {
  asm("mov.b64 {%0,%1},%2;" : "=f"(x), "=f"(y) : "l"(v));
}
__device__ __forceinline__ void fma2(ull& d, ull a, ull b) {
  asm("fma.rn.f32x2 %0,%1,%2,%0;" : "+l"(d) : "l"(a), "l"(b));
}

// msg_m[m][d] = sum_k src[d][m*32+k]  (contiguous float4 loads, shfl tree)
// mkp[k][d]  = sum_{m_loc} src[d][m*32+k]  (contiguous-lane, serial over m)
template <int DIN>
__device__ __forceinline__ void msgs(SM* s, const float* src, float* mkp,
                                     int lane, int wid) {
  for (int r = wid; r < DIN * 8; r += NW) {
    int d = r >> 3, g = r & 7;  // g: group of 4 antennas (128 floats)
    float4 v = *(const float4*)(src + d * 1024 + g * 128 + lane * 4);
    float t = v.x + v.y + v.z + v.w;
    t += __shfl_xor_sync(0xffffffffu, t, 1);
    t += __shfl_xor_sync(0xffffffffu, t, 2);
    t += __shfl_xor_sync(0xffffffffu, t, 4);
    if ((lane & 7) == 0) s->mm[(g * 4 + (lane >> 3)) * 34 + d] = t;
  }
  for (int d = wid; d < DIN; d += NW) {
    float t = 0.f;
#pragma unroll
    for (int m2 = 0; m2 < 32; m2++) t += src[d * 1024 + m2 * 32 + lane];
    mkp[lane * 34 + d] = t;
  }
}

// combine: mkc = mkp(local) + mkp(peer), float2 granularity
template <int DIN>
__device__ __forceinline__ void combine_mk(SM* s, const float* mkp, int tid,
                                           uint32_t peer) {
  constexpr int PAIRS = 32 * DIN / 2;
  for (int i = tid; i < PAIRS; i += NT) {
    int k = i / (DIN / 2), dp = i % (DIN / 2);
    int off = k * 34 + 2 * dp;
    float2 a = *(const float2*)(mkp + off);
    float2 b = peer_ldf2(mkp + off, peer);
    *(float2*)(s->mkc + off) = make_float2(a.x + b.x, a.y + b.y);
  }
}

// One GNN layer, DOUT=32. src = xs (L1) or h (L2-4), dest = h (in place).
template <int DIN>
__device__ __forceinline__ void layer32(SM* s, const float* src,
                                        const float* gWs, const float* gWm,
                                        const float* gWk, int par, int tid,
                                        int lane, int wid, uint32_t peer) {
  float* mkp = s->mkpL[par];
  // stage transposed weights: wT[d*32 + h]
  for (int i = tid; i < DIN * 32; i += NT) {
    int d = i >> 5, hh = i & 31;
    s->wsT[i] = gWs[hh * DIN + d];
    s->wmT[i] = gWm[hh * DIN + d];
    s->wkT[i] = gWk[hh * DIN + d];
  }
  msgs<DIN>(s, src, mkp, lane, wid);
  csync();  // mkp visible cluster-wide; also orders local staging/mm
  combine_mk<DIN>(s, mkp, tid, peer);
  __syncthreads();
  // bias GEMMs (f32x2): bm[mk][h], bk[mk][h]; 512 threads, 1 iter each
  if (tid < 512) {
    const int jj = tid & 15, mk = tid >> 4;
    ull tb = 0, tk = 0;
#pragma unroll
    for (int d = 0; d < DIN; d++) {
      ull wmv = *(const ull*)(s->wmT + d * 32 + 2 * jj);
      ull wkv = *(const ull*)(s->wkT + d * 32 + 2 * jj);
      float am = s->mm[mk * 34 + d];
      float ak = s->mkc[mk * 34 + d];
      fma2(tb, pk2(am, am), wmv);
      fma2(tk, pk2(ak, ak), wkv);
    }
    float a, b;
    upk2(tb, a, b); *(float2*)(s->bm + mk * 34 + 2 * jj) = make_float2(a, b);
    upk2(tk, a, b); *(float2*)(s->bk + mk * 34 + 2 * jj) = make_float2(a, b);
  }
  __syncthreads();

  // ---- edge GEMM: thread = (edge pair, h half); 2 edges x 8 h-pairs ----
  const int idx = tid & 511, hs = tid >> 9;
  const int hb = hs * 16;
  const int e0 = 2 * idx, m = e0 >> 5, k0 = e0 & 31;
  ull a0[8], a1[8];
#pragma unroll
  for (int j = 0; j < 8; j++) {
    float2 bmv = *(const float2*)(s->bm + m * 34 + hb + 2 * j);
    float2 b0v = *(const float2*)(s->bk + k0 * 34 + hb + 2 * j);
    float2 b1v = *(const float2*)(s->bk + (k0 + 1) * 34 + hb + 2 * j);
    a0[j] = pk2(bmv.x + b0v.x, bmv.y + b0v.y);
    a1[j] = pk2(bmv.x + b1v.x, bmv.y + b1v.y);
  }
#pragma unroll 4
  for (int d = 0; d < DIN; d++) {
    float2 hv = *(const float2*)(src + d * 1024 + e0);
    ull H0 = pk2(hv.x, hv.x), H1 = pk2(hv.y, hv.y);
    const ulonglong2* wr = (const ulonglong2*)(s->wsT + d * 32 + hb);
#pragma unroll
    for (int q = 0; q < 4; q++) {
      ulonglong2 w = wr[q];
      fma2(a0[2 * q], H0, w.x);
      fma2(a0[2 * q + 1], H0, w.y);
      fma2(a1[2 * q], H1, w.x);
      fma2(a1[2 * q + 1], H1, w.y);
    }
  }
  __syncthreads();  // other h-half still reads our columns: finish reads first

  // epilogue: relu + store (in place into h)
#pragma unroll
  for (int j = 0; j < 8; j++) {
    float x0, x1, y0, y1;
    upk2(a0[j], x0, x1);
    upk2(a1[j], y0, y1);
    x0 = fmaxf(x0, 0.f); x1 = fmaxf(x1, 0.f);
    y0 = fmaxf(y0, 0.f); y1 = fmaxf(y1, 0.f);
    *(float2*)(s->h + (hb + 2 * j) * 1024 + e0) = make_float2(x0, y0);
    *(float2*)(s->h + (hb + 2 * j + 1) * 1024 + e0) = make_float2(x1, y1);
  }
  __syncthreads();  // h ready for next layer
}

__global__ void __launch_bounds__(NT, 1) __cluster_dims__(2, 1, 1)
gnn_kernel(Params p) {
  SM* s = (SM*)smem_raw;
  const int tid = threadIdx.x, lane = tid & 31, wid = tid >> 5;
  uint32_t rank;
  asm("mov.u32 %0, %%cluster_ctarank;" : "=r"(rank));
  const uint32_t peer = rank ^ 1u;
  const int sample = blockIdx.x >> 1;

  // stage x -> xs[c][e]
  {
    const float* xg = p.x + (size_t)sample * 4096 + (size_t)rank * 2048;
    float2 v = *(const float2*)(xg + 2 * tid);
    s->xs[tid] = v.x;
    s->xs[1024 + tid] = v.y;
  }
  __syncthreads();

  // parities: L1:0 L2:1 L3:0 L4:1 L5:0 (overwrite distance 2 => safe)
  layer32<2>(s, s->xs, p.w[0], p.w[1], p.w[2], 0, tid, lane, wid, peer);
  for (int l = 1; l < 4; ++l)
    layer32<32>(s, s->h, p.w[3 * l], p.w[3 * l + 1], p.w[3 * l + 2], l & 1,
                tid, lane, wid, peer);

  // ---- layer 5 (DIN=32, DOUT=2, no relu) + power norm + store ----
  {
    const float* gWs = p.w[12];
    const float* gWm = p.w[13];
    const float* gWk = p.w[14];
    float* mkp = s->mkpL[0];
    if (tid < 64) {  // transposed stride-2 staging
      int d = tid >> 1, hh = tid & 1;
      s->wsT[d * 2 + hh] = gWs[hh * 32 + d];
      s->wmT[d * 2 + hh] = gWm[hh * 32 + d];
      s->wkT[d * 2 + hh] = gWk[hh * 32 + d];
    }
    msgs<32>(s, s->h, mkp, lane, wid);
    csync();
    combine_mk<32>(s, mkp, tid, peer);
    __syncthreads();
    if (tid < 32) {  // bias: 32 mk x 1 h-pair each
      ull tb = 0, tk = 0;
#pragma unroll
      for (int d = 0; d < 32; d++) {
        ull wmv = *(const ull*)(s->wmT + d * 2);
        ull wkv = *(const ull*)(s->wkT + d * 2);
        float am = s->mm[tid * 34 + d];
        float ak = s->mkc[tid * 34 + d];
        fma2(tb, pk2(am, am), wmv);
        fma2(tk, pk2(ak, ak), wkv);
      }
      float a, b;
      upk2(tb, a, b); *(float2*)(s->bm + tid * 34) = make_float2(a, b);
      upk2(tk, a, b); *(float2*)(s->bk + tid * 34) = make_float2(a, b);
    }
    __syncthreads();

    // 1 edge per thread
    const int e0 = tid, m = e0 >> 5, k0 = e0 & 31;
    float2 bmv = *(const float2*)(s->bm + m * 34);
    float2 bkv = *(const float2*)(s->bk + k0 * 34);
    ull a0 = pk2(bmv.x + bkv.x, bmv.y + bkv.y);
#pragma unroll 8
    for (int d = 0; d < 32; d++) {
      float hv = s->h[d * 1024 + e0];
      ull w = *(const ull*)(s->wsT + d * 2);
      fma2(a0, pk2(hv, hv), w);
    }
    float x0, x1;
    upk2(a0, x0, x1);

    // power = sum over whole sample of z^2
    float pl = x0 * x0 + x1 * x1;
    pl += __shfl_xor_sync(0xffffffffu, pl, 1);
    pl += __shfl_xor_sync(0xffffffffu, pl, 2);
    pl += __shfl_xor_sync(0xffffffffu, pl, 4);
    pl += __shfl_xor_sync(0xffffffffu, pl, 8);
    pl += __shfl_xor_sync(0xffffffffu, pl, 16);
    if (lane == 0) s->red[wid] = pl;
    __syncthreads();
    if (tid == 0) {
      float t = 0.f;
#pragma unroll
      for (int w2 = 0; w2 < NW; w2++) t += s->red[w2];
      s->powslot = t;
    }
    csync();  // both CTAs' powslot ready
    float al = rsqrtf(s->powslot + peer_ldf(&s->powslot, peer));  // PT = 1

    *(float2*)(p.out + (size_t)sample * 4096 + (size_t)rank * 2048 + 2 * tid) =
        make_float2(al * x0, al * x1);
    csync();  // keep our smem alive until peer finished its powslot read
  }
}

extern "C" void kernel_launch(void* const* d_in, const int* in_sizes, int n_in,
                              void* d_out, int out_size) {
  Params p;
  p.x = (const float*)d_in[0];
  for (int i = 0; i < 15; i++) p.w[i] = (const float*)d_in[1 + i];
  p.out = (float*)d_out;
  cudaFuncSetAttribute(gnn_kernel, cudaFuncAttributeMaxDynamicSharedMemorySize,
                       (int)sizeof(SM));
  gnn_kernel<<<2048, NT, sizeof(SM)>>>(p);
}